// round 1
// baseline (speedup 1.0000x reference)
#include <cuda_runtime.h>
#include <math.h>

// Problem constants
#define B_     16
#define HH     28
#define WW     28
#define HW     784
#define C_ALL  3072
#define C4     2048
#define C3     1024
#define H4     14
#define HW4    196
#define NL     9
#define NK     2000

// Partition of the channel dim for the ab (landmark logit) pass
#define NCH    24
#define CCH    128   // channels per chunk; 16 chunks cover l4, 8 cover l3

// Output layout: class_scores (16*2000), maps (16*9*784), all_features (16*3072*9)
#define CLS_OFF  0
#define MAPS_OFF (B_*NK)                  // 32000
#define FEAT_OFF (MAPS_OFF + B_*NL*HW)    // 144896

// Scratch (static __device__ arrays: allocation-free)
__device__ float g_asq[NL];
__device__ float g_part[(size_t)B_*HW*NCH*NL];   // ~10.8 MB partial ab sums
__device__ float g_modavg[(size_t)C_ALL*B_];     // [c][b] transposed for float4 reads

// ---------------------------------------------------------------------------
// K0: a_sq[l] = ||W_land[l]||^2
// ---------------------------------------------------------------------------
__global__ void k_asq(const float* __restrict__ Wl) {
    int warp = threadIdx.x >> 5, lane = threadIdx.x & 31;
    if (warp < NL) {
        float s = 0.f;
        for (int i = lane; i < C_ALL; i += 32) {
            float w = Wl[warp * C_ALL + i];
            s = fmaf(w, w, s);
        }
        #pragma unroll
        for (int o = 16; o; o >>= 1) s += __shfl_xor_sync(0xffffffffu, s, o);
        if (lane == 0) g_asq[warp] = s;
    }
}

// ---------------------------------------------------------------------------
// K1: partial ab[b,l,px] over a channel chunk. Block = (chunk, b), 196 threads,
// each thread owns 4 consecutive pixels (196*4 = 784 = full image).
// l4 channels are upsampled on the fly from SMEM-staged 14x14 rows.
// ---------------------------------------------------------------------------
__global__ __launch_bounds__(196) void k_ab(const float* __restrict__ l3,
                                            const float* __restrict__ l4,
                                            const float* __restrict__ Wl) {
    __shared__ float sW[NL * CCH];      // 4.5 KB
    __shared__ float sRow[8 * HW4];     // 6.1 KB: 8 staged l4 channel rows

    int b = blockIdx.y, chunk = blockIdx.x;
    int c0 = chunk * CCH;
    int tid = threadIdx.x;

    for (int i = tid; i < NL * CCH; i += 196) {
        int l = i / CCH, cc = i - l * CCH;
        sW[i] = Wl[l * C_ALL + c0 + cc];
    }

    int px = tid * 4;
    int py = px / WW, pxx = px - py * WW;

    float acc[NL][4];
    #pragma unroll
    for (int l = 0; l < NL; l++)
        #pragma unroll
        for (int j = 0; j < 4; j++) acc[l][j] = 0.f;

    if (chunk < 16) {
        // ---- l4 region: bilinear upsample (half-pixel centers, edge-renorm) ----
        float cyf = 0.5f * (float)py - 0.25f;
        int iyf = (int)floorf(cyf);
        float wy = cyf - (float)iyf;
        int iy0 = iyf < 0 ? 0 : iyf;
        int iy1 = (iyf + 1) > 13 ? 13 : (iyf + 1);

        int oa0[4], oa1[4], ob0[4], ob1[4];
        float wx[4];
        #pragma unroll
        for (int j = 0; j < 4; j++) {
            float cxf = 0.5f * (float)(pxx + j) - 0.25f;
            int ixf = (int)floorf(cxf);
            wx[j] = cxf - (float)ixf;
            int x0 = ixf < 0 ? 0 : ixf;
            int x1 = (ixf + 1) > 13 ? 13 : (ixf + 1);
            oa0[j] = iy0 * H4 + x0; oa1[j] = iy0 * H4 + x1;
            ob0[j] = iy1 * H4 + x0; ob1[j] = iy1 * H4 + x1;
        }

        const float* l4b = l4 + ((size_t)b * C4 + c0) * HW4;
        __syncthreads();                       // sW visible
        for (int cg = 0; cg < CCH; cg += 8) {
            const float4* src = (const float4*)(l4b + (size_t)cg * HW4);
            ((float4*)sRow)[tid]       = src[tid];
            ((float4*)sRow)[tid + 196] = src[tid + 196];
            __syncthreads();
            #pragma unroll
            for (int cc = 0; cc < 8; cc++) {
                const float* r = sRow + cc * HW4;
                float xv[4];
                #pragma unroll
                for (int j = 0; j < 4; j++) {
                    float a0 = r[oa0[j]], a1 = r[oa1[j]];
                    float b0 = r[ob0[j]], b1 = r[ob1[j]];
                    float t = fmaf(wx[j], a1 - a0, a0);
                    float u = fmaf(wx[j], b1 - b0, b0);
                    xv[j] = fmaf(wy, u - t, t);
                }
                int c = cg + cc;
                #pragma unroll
                for (int l = 0; l < NL; l++) {
                    float w = sW[l * CCH + c];
                    #pragma unroll
                    for (int j = 0; j < 4; j++)
                        acc[l][j] = fmaf(w, xv[j], acc[l][j]);
                }
            }
            __syncthreads();
        }
    } else {
        // ---- l3 region: direct coalesced float4 loads ----
        __syncthreads();                       // sW visible
        const float* x3 = l3 + ((size_t)b * C3 + (c0 - C4)) * HW + px;
        for (int c = 0; c < CCH; c++) {
            float4 xv = *(const float4*)(x3 + (size_t)c * HW);
            #pragma unroll
            for (int l = 0; l < NL; l++) {
                float w = sW[l * CCH + c];
                acc[l][0] = fmaf(w, xv.x, acc[l][0]);
                acc[l][1] = fmaf(w, xv.y, acc[l][1]);
                acc[l][2] = fmaf(w, xv.z, acc[l][2]);
                acc[l][3] = fmaf(w, xv.w, acc[l][3]);
            }
        }
    }

    #pragma unroll
    for (int j = 0; j < 4; j++) {
        float* dst = g_part + (((size_t)(b * HW + px + j)) * NCH + chunk) * NL;
        #pragma unroll
        for (int l = 0; l < NL; l++) dst[l] = acc[l][j];
    }
}

// ---------------------------------------------------------------------------
// K2: sum partials, logits = 2*ab - a_sq (b_sq cancels in softmax), softmax,
// write maps to d_out.
// ---------------------------------------------------------------------------
__global__ void k_softmax(float* __restrict__ out) {
    int idx = blockIdx.x * blockDim.x + threadIdx.x;
    if (idx >= B_ * HW) return;
    int b = idx / HW, px = idx - b * HW;

    float s[NL];
    #pragma unroll
    for (int l = 0; l < NL; l++) s[l] = 0.f;

    const float4* p4 = (const float4*)(g_part + (size_t)idx * NCH * NL);
    #pragma unroll
    for (int i = 0; i < (NCH * NL) / 4; i++) {
        float4 v = p4[i];
        s[(4 * i + 0) % NL] += v.x;
        s[(4 * i + 1) % NL] += v.y;
        s[(4 * i + 2) % NL] += v.z;
        s[(4 * i + 3) % NL] += v.w;
    }

    float lg[NL], m = -1e30f;
    #pragma unroll
    for (int l = 0; l < NL; l++) {
        lg[l] = 2.f * s[l] - g_asq[l];
        m = fmaxf(m, lg[l]);
    }
    float e[NL], den = 0.f;
    #pragma unroll
    for (int l = 0; l < NL; l++) { e[l] = __expf(lg[l] - m); den += e[l]; }
    float inv = 1.f / den;

    float* mp = out + MAPS_OFF + (size_t)b * NL * HW + px;
    #pragma unroll
    for (int l = 0; l < NL; l++) mp[(size_t)l * HW] = e[l] * inv;
}

// ---------------------------------------------------------------------------
// K3: all_features[b,c,l] = (1/784) * sum_px maps[b,l,px] * x[b,c,px].
// Block = (cblk of 32 channels, b); 8 warps, each warp owns 4 channels;
// maps staged once in SMEM, l4 rows staged per-warp, maps loads amortized
// over the 4 channels.
// ---------------------------------------------------------------------------
__global__ __launch_bounds__(256) void k_feat(const float* __restrict__ l3,
                                              const float* __restrict__ l4,
                                              float* __restrict__ out) {
    extern __shared__ float sm[];
    float* sMaps = sm;                 // NL*HW = 7056 floats
    float* sL4   = sm + NL * HW;       // 8 warps * 4 ch * 196 = 6272 floats

    int b = blockIdx.y, cblk = blockIdx.x;
    int tid = threadIdx.x, warp = tid >> 5, lane = tid & 31;

    const float* mp = out + MAPS_OFF + (size_t)b * NL * HW;
    for (int i = tid; i < NL * HW; i += 256) sMaps[i] = mp[i];
    __syncthreads();

    int cbase = cblk * 32 + warp * 4;
    float acc[4][NL];
    #pragma unroll
    for (int ch = 0; ch < 4; ch++)
        #pragma unroll
        for (int l = 0; l < NL; l++) acc[ch][l] = 0.f;

    if (cbase < C4) {
        float* st = sL4 + warp * (4 * HW4);
        #pragma unroll
        for (int ch = 0; ch < 4; ch++) {
            const float* row = l4 + ((size_t)b * C4 + cbase + ch) * HW4;
            for (int i = lane; i < HW4; i += 32) st[ch * HW4 + i] = row[i];
        }
        __syncwarp();
        for (int px = lane; px < HW; px += 32) {
            int py = px / WW, pxx = px - py * WW;
            float cyf = 0.5f * (float)py - 0.25f;
            int iyf = (int)floorf(cyf);
            float wy = cyf - (float)iyf;
            int iy0 = iyf < 0 ? 0 : iyf;
            int iy1 = (iyf + 1) > 13 ? 13 : (iyf + 1);
            float cxf = 0.5f * (float)pxx - 0.25f;
            int ixf = (int)floorf(cxf);
            float wx = cxf - (float)ixf;
            int ix0 = ixf < 0 ? 0 : ixf;
            int ix1 = (ixf + 1) > 13 ? 13 : (ixf + 1);
            int oa0 = iy0 * H4 + ix0, oa1 = iy0 * H4 + ix1;
            int ob0 = iy1 * H4 + ix0, ob1 = iy1 * H4 + ix1;

            float m9[NL];
            #pragma unroll
            for (int l = 0; l < NL; l++) m9[l] = sMaps[l * HW + px];

            #pragma unroll
            for (int ch = 0; ch < 4; ch++) {
                const float* r = st + ch * HW4;
                float a0 = r[oa0], a1 = r[oa1], b0 = r[ob0], b1 = r[ob1];
                float t = fmaf(wx, a1 - a0, a0);
                float u = fmaf(wx, b1 - b0, b0);
                float xv = fmaf(wy, u - t, t);
                #pragma unroll
                for (int l = 0; l < NL; l++)
                    acc[ch][l] = fmaf(xv, m9[l], acc[ch][l]);
            }
        }
    } else {
        const float* x3 = l3 + ((size_t)b * C3 + (cbase - C4)) * HW;
        for (int px = lane; px < HW; px += 32) {
            float m9[NL];
            #pragma unroll
            for (int l = 0; l < NL; l++) m9[l] = sMaps[l * HW + px];
            #pragma unroll
            for (int ch = 0; ch < 4; ch++) {
                float xv = x3[(size_t)ch * HW + px];
                #pragma unroll
                for (int l = 0; l < NL; l++)
                    acc[ch][l] = fmaf(xv, m9[l], acc[ch][l]);
            }
        }
    }

    #pragma unroll
    for (int ch = 0; ch < 4; ch++)
        #pragma unroll
        for (int l = 0; l < NL; l++) {
            float v = acc[ch][l];
            #pragma unroll
            for (int o = 16; o; o >>= 1) v += __shfl_xor_sync(0xffffffffu, v, o);
            acc[ch][l] = v;
        }

    if (lane == 0) {
        const float sc = 1.0f / (float)HW;
        #pragma unroll
        for (int ch = 0; ch < 4; ch++)
            #pragma unroll
            for (int l = 0; l < NL; l++)
                out[FEAT_OFF + ((size_t)b * C_ALL + cbase + ch) * NL + l] =
                    acc[ch][l] * sc;
    }
}

// ---------------------------------------------------------------------------
// K4: mod_avg[c][b] = (1/8) * sum_{l<8} feat[b,c,l] * modulation[c,l]
// (stored transposed so K5 can read 16 batches as 4x float4)
// ---------------------------------------------------------------------------
__global__ void k_modavg(const float* __restrict__ mod, const float* __restrict__ out) {
    int idx = blockIdx.x * 256 + threadIdx.x;
    if (idx >= C_ALL * B_) return;
    int c = idx >> 4, b = idx & 15;
    const float* f = out + FEAT_OFF + ((size_t)b * C_ALL + c) * NL;
    const float* md = mod + c * NL;
    float s = 0.f;
    #pragma unroll
    for (int l = 0; l < 8; l++) s = fmaf(f[l], md[l], s);
    g_modavg[(size_t)c * B_ + b] = s * 0.125f;
}

// ---------------------------------------------------------------------------
// K5: class_scores[b,k] = sum_c W_class[k,c] * mod_avg[c][b]
// Block per k; coalesced W_class row read; 16 batch accumulators.
// ---------------------------------------------------------------------------
__global__ __launch_bounds__(256) void k_cls(const float* __restrict__ Wc,
                                             float* __restrict__ out) {
    int k = blockIdx.x, tid = threadIdx.x, warp = tid >> 5, lane = tid & 31;
    const float* wr = Wc + (size_t)k * C_ALL;

    float acc[B_];
    #pragma unroll
    for (int b = 0; b < B_; b++) acc[b] = 0.f;

    for (int c = tid; c < C_ALL; c += 256) {
        float w = wr[c];
        const float4* mv = (const float4*)(g_modavg + (size_t)c * B_);
        #pragma unroll
        for (int q = 0; q < 4; q++) {
            float4 m = mv[q];
            acc[4 * q + 0] = fmaf(w, m.x, acc[4 * q + 0]);
            acc[4 * q + 1] = fmaf(w, m.y, acc[4 * q + 1]);
            acc[4 * q + 2] = fmaf(w, m.z, acc[4 * q + 2]);
            acc[4 * q + 3] = fmaf(w, m.w, acc[4 * q + 3]);
        }
    }

    __shared__ float red[8][B_];
    #pragma unroll
    for (int b = 0; b < B_; b++) {
        float v = acc[b];
        #pragma unroll
        for (int o = 16; o; o >>= 1) v += __shfl_xor_sync(0xffffffffu, v, o);
        acc[b] = v;
    }
    if (lane == 0)
        #pragma unroll
        for (int b = 0; b < B_; b++) red[warp][b] = acc[b];
    __syncthreads();
    if (tid < B_) {
        float s = 0.f;
        #pragma unroll
        for (int w = 0; w < 8; w++) s += red[w][tid];
        out[(size_t)tid * NK + k] = s;
    }
}

// ---------------------------------------------------------------------------
extern "C" void kernel_launch(void* const* d_in, const int* in_sizes, int n_in,
                              void* d_out, int out_size) {
    const float* l3  = (const float*)d_in[0];
    const float* l4  = (const float*)d_in[1];
    const float* Wl  = (const float*)d_in[2];
    const float* Wc  = (const float*)d_in[3];
    const float* mod = (const float*)d_in[4];
    float* out = (float*)d_out;

    k_asq<<<1, 288>>>(Wl);
    k_ab<<<dim3(NCH, B_), 196>>>(l3, l4, Wl);
    k_softmax<<<(B_ * HW + 255) / 256, 256>>>(out);

    size_t sm3 = (size_t)(NL * HW + 8 * 4 * HW4) * sizeof(float);  // 53312 B
    cudaFuncSetAttribute(k_feat, cudaFuncAttributeMaxDynamicSharedMemorySize, (int)sm3);
    k_feat<<<dim3(96, B_), 256, sm3>>>(l3, l4, out);

    k_modavg<<<(C_ALL * B_ + 255) / 256, 256>>>(mod, out);
    k_cls<<<NK, 256>>>(Wc, out);
}

// round 2
// speedup vs baseline: 1.0023x; 1.0023x over previous
#include <cuda_runtime.h>
#include <math.h>

// Problem constants
#define B_     16
#define HH     28
#define WW     28
#define HW     784
#define C_ALL  3072
#define C4     2048
#define C3     1024
#define H4     14
#define HW4    196
#define NL     9
#define NK     2000

// Partition of the channel dim for the ab (landmark logit) pass
#define NCH    24
#define CCH    128   // channels per chunk; 16 chunks cover l4, 8 cover l3

// Output layout: class_scores (16*2000), maps (16*9*784), all_features (16*3072*9)
#define CLS_OFF  0
#define MAPS_OFF (B_*NK)                  // 32000
#define FEAT_OFF (MAPS_OFF + B_*NL*HW)    // 144896

// Scratch (static __device__ arrays: allocation-free)
__device__ float g_asq[NL];
__device__ float g_part[(size_t)B_*HW*NCH*NL];   // ~10.8 MB partial ab sums
__device__ float g_modavg[(size_t)C_ALL*B_];     // [c][b] transposed for float4 reads

// ---------------------------------------------------------------------------
// K0: a_sq[l] = ||W_land[l]||^2
// ---------------------------------------------------------------------------
__global__ void k_asq(const float* __restrict__ Wl) {
    int warp = threadIdx.x >> 5, lane = threadIdx.x & 31;
    if (warp < NL) {
        float s = 0.f;
        for (int i = lane; i < C_ALL; i += 32) {
            float w = Wl[warp * C_ALL + i];
            s = fmaf(w, w, s);
        }
        #pragma unroll
        for (int o = 16; o; o >>= 1) s += __shfl_xor_sync(0xffffffffu, s, o);
        if (lane == 0) g_asq[warp] = s;
    }
}

// ---------------------------------------------------------------------------
// K1: partial ab[b,l,px] over a channel chunk. Block = (chunk, b), 196 threads,
// each thread owns 4 consecutive pixels (196*4 = 784 = full image).
// l4 channels are upsampled on the fly from SMEM-staged 14x14 rows.
// ---------------------------------------------------------------------------
__global__ __launch_bounds__(196) void k_ab(const float* __restrict__ l3,
                                            const float* __restrict__ l4,
                                            const float* __restrict__ Wl) {
    __shared__ float sW[NL * CCH];      // 4.5 KB
    __shared__ float sRow[8 * HW4];     // 6.1 KB: 8 staged l4 channel rows

    int b = blockIdx.y, chunk = blockIdx.x;
    int c0 = chunk * CCH;
    int tid = threadIdx.x;

    for (int i = tid; i < NL * CCH; i += 196) {
        int l = i / CCH, cc = i - l * CCH;
        sW[i] = Wl[l * C_ALL + c0 + cc];
    }

    int px = tid * 4;
    int py = px / WW, pxx = px - py * WW;

    float acc[NL][4];
    #pragma unroll
    for (int l = 0; l < NL; l++)
        #pragma unroll
        for (int j = 0; j < 4; j++) acc[l][j] = 0.f;

    if (chunk < 16) {
        // ---- l4 region: bilinear upsample (half-pixel centers, edge-renorm) ----
        float cyf = 0.5f * (float)py - 0.25f;
        int iyf = (int)floorf(cyf);
        float wy = cyf - (float)iyf;
        int iy0 = iyf < 0 ? 0 : iyf;
        int iy1 = (iyf + 1) > 13 ? 13 : (iyf + 1);

        int oa0[4], oa1[4], ob0[4], ob1[4];
        float wx[4];
        #pragma unroll
        for (int j = 0; j < 4; j++) {
            float cxf = 0.5f * (float)(pxx + j) - 0.25f;
            int ixf = (int)floorf(cxf);
            wx[j] = cxf - (float)ixf;
            int x0 = ixf < 0 ? 0 : ixf;
            int x1 = (ixf + 1) > 13 ? 13 : (ixf + 1);
            oa0[j] = iy0 * H4 + x0; oa1[j] = iy0 * H4 + x1;
            ob0[j] = iy1 * H4 + x0; ob1[j] = iy1 * H4 + x1;
        }

        const float* l4b = l4 + ((size_t)b * C4 + c0) * HW4;
        __syncthreads();                       // sW visible
        for (int cg = 0; cg < CCH; cg += 8) {
            const float4* src = (const float4*)(l4b + (size_t)cg * HW4);
            ((float4*)sRow)[tid]       = src[tid];
            ((float4*)sRow)[tid + 196] = src[tid + 196];
            __syncthreads();
            #pragma unroll
            for (int cc = 0; cc < 8; cc++) {
                const float* r = sRow + cc * HW4;
                float xv[4];
                #pragma unroll
                for (int j = 0; j < 4; j++) {
                    float a0 = r[oa0[j]], a1 = r[oa1[j]];
                    float b0 = r[ob0[j]], b1 = r[ob1[j]];
                    float t = fmaf(wx[j], a1 - a0, a0);
                    float u = fmaf(wx[j], b1 - b0, b0);
                    xv[j] = fmaf(wy, u - t, t);
                }
                int c = cg + cc;
                #pragma unroll
                for (int l = 0; l < NL; l++) {
                    float w = sW[l * CCH + c];
                    #pragma unroll
                    for (int j = 0; j < 4; j++)
                        acc[l][j] = fmaf(w, xv[j], acc[l][j]);
                }
            }
            __syncthreads();
        }
    } else {
        // ---- l3 region: direct coalesced float4 loads ----
        __syncthreads();                       // sW visible
        const float* x3 = l3 + ((size_t)b * C3 + (c0 - C4)) * HW + px;
        for (int c = 0; c < CCH; c++) {
            float4 xv = *(const float4*)(x3 + (size_t)c * HW);
            #pragma unroll
            for (int l = 0; l < NL; l++) {
                float w = sW[l * CCH + c];
                acc[l][0] = fmaf(w, xv.x, acc[l][0]);
                acc[l][1] = fmaf(w, xv.y, acc[l][1]);
                acc[l][2] = fmaf(w, xv.z, acc[l][2]);
                acc[l][3] = fmaf(w, xv.w, acc[l][3]);
            }
        }
    }

    #pragma unroll
    for (int j = 0; j < 4; j++) {
        float* dst = g_part + (((size_t)(b * HW + px + j)) * NCH + chunk) * NL;
        #pragma unroll
        for (int l = 0; l < NL; l++) dst[l] = acc[l][j];
    }
}

// ---------------------------------------------------------------------------
// K2: sum partials, logits = 2*ab - a_sq (b_sq cancels in softmax), softmax,
// write maps to d_out.
// ---------------------------------------------------------------------------
__global__ void k_softmax(float* __restrict__ out) {
    int idx = blockIdx.x * blockDim.x + threadIdx.x;
    if (idx >= B_ * HW) return;
    int b = idx / HW, px = idx - b * HW;

    float s[NL];
    #pragma unroll
    for (int l = 0; l < NL; l++) s[l] = 0.f;

    const float4* p4 = (const float4*)(g_part + (size_t)idx * NCH * NL);
    #pragma unroll
    for (int i = 0; i < (NCH * NL) / 4; i++) {
        float4 v = p4[i];
        s[(4 * i + 0) % NL] += v.x;
        s[(4 * i + 1) % NL] += v.y;
        s[(4 * i + 2) % NL] += v.z;
        s[(4 * i + 3) % NL] += v.w;
    }

    float lg[NL], m = -1e30f;
    #pragma unroll
    for (int l = 0; l < NL; l++) {
        lg[l] = 2.f * s[l] - g_asq[l];
        m = fmaxf(m, lg[l]);
    }
    float e[NL], den = 0.f;
    #pragma unroll
    for (int l = 0; l < NL; l++) { e[l] = __expf(lg[l] - m); den += e[l]; }
    float inv = 1.f / den;

    float* mp = out + MAPS_OFF + (size_t)b * NL * HW + px;
    #pragma unroll
    for (int l = 0; l < NL; l++) mp[(size_t)l * HW] = e[l] * inv;
}

// ---------------------------------------------------------------------------
// K3: all_features[b,c,l] = (1/784) * sum_px maps[b,l,px] * x[b,c,px].
// Block = (cblk of 32 channels, b); 8 warps, each warp owns 4 channels;
// maps staged once in SMEM, l4 rows staged per-warp, maps loads amortized
// over the 4 channels.
// ---------------------------------------------------------------------------
__global__ __launch_bounds__(256) void k_feat(const float* __restrict__ l3,
                                              const float* __restrict__ l4,
                                              float* __restrict__ out) {
    extern __shared__ float sm[];
    float* sMaps = sm;                 // NL*HW = 7056 floats
    float* sL4   = sm + NL * HW;       // 8 warps * 4 ch * 196 = 6272 floats

    int b = blockIdx.y, cblk = blockIdx.x;
    int tid = threadIdx.x, warp = tid >> 5, lane = tid & 31;

    const float* mp = out + MAPS_OFF + (size_t)b * NL * HW;
    for (int i = tid; i < NL * HW; i += 256) sMaps[i] = mp[i];
    __syncthreads();

    int cbase = cblk * 32 + warp * 4;
    float acc[4][NL];
    #pragma unroll
    for (int ch = 0; ch < 4; ch++)
        #pragma unroll
        for (int l = 0; l < NL; l++) acc[ch][l] = 0.f;

    if (cbase < C4) {
        float* st = sL4 + warp * (4 * HW4);
        #pragma unroll
        for (int ch = 0; ch < 4; ch++) {
            const float* row = l4 + ((size_t)b * C4 + cbase + ch) * HW4;
            for (int i = lane; i < HW4; i += 32) st[ch * HW4 + i] = row[i];
        }
        __syncwarp();
        for (int px = lane; px < HW; px += 32) {
            int py = px / WW, pxx = px - py * WW;
            float cyf = 0.5f * (float)py - 0.25f;
            int iyf = (int)floorf(cyf);
            float wy = cyf - (float)iyf;
            int iy0 = iyf < 0 ? 0 : iyf;
            int iy1 = (iyf + 1) > 13 ? 13 : (iyf + 1);
            float cxf = 0.5f * (float)pxx - 0.25f;
            int ixf = (int)floorf(cxf);
            float wx = cxf - (float)ixf;
            int ix0 = ixf < 0 ? 0 : ixf;
            int ix1 = (ixf + 1) > 13 ? 13 : (ixf + 1);
            int oa0 = iy0 * H4 + ix0, oa1 = iy0 * H4 + ix1;
            int ob0 = iy1 * H4 + ix0, ob1 = iy1 * H4 + ix1;

            float m9[NL];
            #pragma unroll
            for (int l = 0; l < NL; l++) m9[l] = sMaps[l * HW + px];

            #pragma unroll
            for (int ch = 0; ch < 4; ch++) {
                const float* r = st + ch * HW4;
                float a0 = r[oa0], a1 = r[oa1], b0 = r[ob0], b1 = r[ob1];
                float t = fmaf(wx, a1 - a0, a0);
                float u = fmaf(wx, b1 - b0, b0);
                float xv = fmaf(wy, u - t, t);
                #pragma unroll
                for (int l = 0; l < NL; l++)
                    acc[ch][l] = fmaf(xv, m9[l], acc[ch][l]);
            }
        }
    } else {
        const float* x3 = l3 + ((size_t)b * C3 + (cbase - C4)) * HW;
        for (int px = lane; px < HW; px += 32) {
            float m9[NL];
            #pragma unroll
            for (int l = 0; l < NL; l++) m9[l] = sMaps[l * HW + px];
            #pragma unroll
            for (int ch = 0; ch < 4; ch++) {
                float xv = x3[(size_t)ch * HW + px];
                #pragma unroll
                for (int l = 0; l < NL; l++)
                    acc[ch][l] = fmaf(xv, m9[l], acc[ch][l]);
            }
        }
    }

    #pragma unroll
    for (int ch = 0; ch < 4; ch++)
        #pragma unroll
        for (int l = 0; l < NL; l++) {
            float v = acc[ch][l];
            #pragma unroll
            for (int o = 16; o; o >>= 1) v += __shfl_xor_sync(0xffffffffu, v, o);
            acc[ch][l] = v;
        }

    if (lane == 0) {
        const float sc = 1.0f / (float)HW;
        #pragma unroll
        for (int ch = 0; ch < 4; ch++)
            #pragma unroll
            for (int l = 0; l < NL; l++)
                out[FEAT_OFF + ((size_t)b * C_ALL + cbase + ch) * NL + l] =
                    acc[ch][l] * sc;
    }
}

// ---------------------------------------------------------------------------
// K4: mod_avg[c][b] = (1/8) * sum_{l<8} feat[b,c,l] * modulation[c,l]
// (stored transposed so K5 can read 16 batches as 4x float4)
// ---------------------------------------------------------------------------
__global__ void k_modavg(const float* __restrict__ mod, const float* __restrict__ out) {
    int idx = blockIdx.x * 256 + threadIdx.x;
    if (idx >= C_ALL * B_) return;
    int c = idx >> 4, b = idx & 15;
    const float* f = out + FEAT_OFF + ((size_t)b * C_ALL + c) * NL;
    const float* md = mod + c * NL;
    float s = 0.f;
    #pragma unroll
    for (int l = 0; l < 8; l++) s = fmaf(f[l], md[l], s);
    g_modavg[(size_t)c * B_ + b] = s * 0.125f;
}

// ---------------------------------------------------------------------------
// K5: class_scores[b,k] = sum_c W_class[k,c] * mod_avg[c][b]
// Block per k; coalesced W_class row read; 16 batch accumulators.
// ---------------------------------------------------------------------------
__global__ __launch_bounds__(256) void k_cls(const float* __restrict__ Wc,
                                             float* __restrict__ out) {
    int k = blockIdx.x, tid = threadIdx.x, warp = tid >> 5, lane = tid & 31;
    const float* wr = Wc + (size_t)k * C_ALL;

    float acc[B_];
    #pragma unroll
    for (int b = 0; b < B_; b++) acc[b] = 0.f;

    for (int c = tid; c < C_ALL; c += 256) {
        float w = wr[c];
        const float4* mv = (const float4*)(g_modavg + (size_t)c * B_);
        #pragma unroll
        for (int q = 0; q < 4; q++) {
            float4 m = mv[q];
            acc[4 * q + 0] = fmaf(w, m.x, acc[4 * q + 0]);
            acc[4 * q + 1] = fmaf(w, m.y, acc[4 * q + 1]);
            acc[4 * q + 2] = fmaf(w, m.z, acc[4 * q + 2]);
            acc[4 * q + 3] = fmaf(w, m.w, acc[4 * q + 3]);
        }
    }

    __shared__ float red[8][B_];
    #pragma unroll
    for (int b = 0; b < B_; b++) {
        float v = acc[b];
        #pragma unroll
        for (int o = 16; o; o >>= 1) v += __shfl_xor_sync(0xffffffffu, v, o);
        acc[b] = v;
    }
    if (lane == 0)
        #pragma unroll
        for (int b = 0; b < B_; b++) red[warp][b] = acc[b];
    __syncthreads();
    if (tid < B_) {
        float s = 0.f;
        #pragma unroll
        for (int w = 0; w < 8; w++) s += red[w][tid];
        out[(size_t)tid * NK + k] = s;
    }
}

// ---------------------------------------------------------------------------
extern "C" void kernel_launch(void* const* d_in, const int* in_sizes, int n_in,
                              void* d_out, int out_size) {
    const float* l3  = (const float*)d_in[0];
    const float* l4  = (const float*)d_in[1];
    const float* Wl  = (const float*)d_in[2];
    const float* Wc  = (const float*)d_in[3];
    const float* mod = (const float*)d_in[4];
    float* out = (float*)d_out;

    k_asq<<<1, 288>>>(Wl);
    k_ab<<<dim3(NCH, B_), 196>>>(l3, l4, Wl);
    k_softmax<<<(B_ * HW + 255) / 256, 256>>>(out);

    size_t sm3 = (size_t)(NL * HW + 8 * 4 * HW4) * sizeof(float);  // 53312 B
    cudaFuncSetAttribute(k_feat, cudaFuncAttributeMaxDynamicSharedMemorySize, (int)sm3);
    k_feat<<<dim3(96, B_), 256, sm3>>>(l3, l4, out);

    k_modavg<<<(C_ALL * B_ + 255) / 256, 256>>>(mod, out);
    k_cls<<<NK, 256>>>(Wc, out);
}